// round 12
// baseline (speedup 1.0000x reference)
#include <cuda_runtime.h>
#include <cuda_bf16.h>
#include <cstdint>

#define SELU_SC 1.0507009873554805f
#define SELU_AL 1.6732632423543772f
#define SELU_SA (SELU_SC * SELU_AL)
#define RES_SC  0.70710678118654752440f
#define LOG2E   1.4426950408889634f
#define LN2     0.6931471805599453f
#define SC_LN2  (SELU_SC * LN2)
#define Q_SC    (0.25f * LOG2E)

__device__ __forceinline__ float selu_f(float v) {
    float p = fmaxf(v, 0.0f);
    float m = fminf(v, 0.0f);
    float e = __expf(m);
    return fmaf(SELU_SA, e, fmaf(SELU_SC, p, -SELU_SA));
}
// selu on input pre-scaled by log2e
__device__ __forceinline__ float selu_s(float s) {
    float p = fmaxf(s, 0.0f);
    float m = fminf(s, 0.0f);
    float e;
    asm("ex2.approx.ftz.f32 %0, %1;" : "=f"(e) : "f"(m));
    return fmaf(SELU_SA, e, fmaf(SC_LN2, p, -SELU_SA));
}

__constant__ int c_occ[21] = {65,66,67,68,69,70,71,72,73,74,75,76,77,
                              81,82,83,84,88,89,90,94};

__device__ float g_x[8 * 128 * 500];
__device__ float g_q[8 * 500 * 128];   // transposed: [b][t][dd]

// hi/lo bf16 split pack: hi = {b(a), b(b)}, lo = residuals
__device__ __forceinline__ void packhl(float a, float b, uint32_t& hi, uint32_t& lo) {
    __nv_bfloat16 ha = __float2bfloat16(a), hb = __float2bfloat16(b);
    float ra = a - __bfloat162float(ha);
    float rb = b - __bfloat162float(hb);
    __nv_bfloat16 la = __float2bfloat16(ra), lb = __float2bfloat16(rb);
    uint16_t ua = *reinterpret_cast<uint16_t*>(&ha);
    uint16_t ub = *reinterpret_cast<uint16_t*>(&hb);
    uint16_t va = *reinterpret_cast<uint16_t*>(&la);
    uint16_t vb = *reinterpret_cast<uint16_t*>(&lb);
    hi = ((uint32_t)ub << 16) | ua;
    lo = ((uint32_t)vb << 16) | va;
}

__device__ __forceinline__ void mma_bf16(float c[4], const uint32_t a[4],
                                         const uint32_t b[2]) {
    asm volatile(
        "mma.sync.aligned.m16n8k16.row.col.f32.bf16.bf16.f32 "
        "{%0,%1,%2,%3}, {%4,%5,%6,%7}, {%8,%9}, {%0,%1,%2,%3};"
        : "+f"(c[0]), "+f"(c[1]), "+f"(c[2]), "+f"(c[3])
        : "r"(a[0]), "r"(a[1]), "r"(a[2]), "r"(a[3]), "r"(b[0]), "r"(b[1]));
}

// ---------------------------------------------------------------------------
// Q kernel — writes Q TRANSPOSED: qout[b][t][dd]
// ---------------------------------------------------------------------------
__global__ __launch_bounds__(128)
void q_kernel(const float* __restrict__ x, const float* __restrict__ wq,
              float* __restrict__ qout) {
    const int dg = blockIdx.x;
    const int tstart = blockIdx.y * 256;
    const int b = blockIdx.z;
    const int tid = threadIdx.x;

    __shared__ float xo[21 * 264];
    __shared__ float ws[16 * 189];

    for (int i = tid; i < 21 * 264; i += 128) {
        int o = i / 264, tt = i % 264;
        int g = tstart + tt - 4;
        xo[i] = (g >= 0 && g < 500) ? x[(b * 128 + c_occ[o]) * 500 + g] : 0.0f;
    }
    for (int i = tid; i < 16 * 189; i += 128)
        ws[i] = wq[dg * 16 * 189 + i];
    __syncthreads();

    float acc0[16], acc1[16];
#pragma unroll
    for (int i = 0; i < 16; i++) { acc0[i] = 0.0f; acc1[i] = 0.0f; }

#pragma unroll 1
    for (int o = 0; o < 21; o++) {
        float xa[9], xb[9];
#pragma unroll
        for (int k = 0; k < 9; k++) {
            xa[k] = xo[o * 264 + tid + k];
            xb[k] = xo[o * 264 + tid + 128 + k];
        }
#pragma unroll
        for (int dc = 0; dc < 16; dc++) {
#pragma unroll
            for (int k = 0; k < 9; k++) {
                float w = ws[dc * 189 + o * 9 + k];
                acc0[dc] = fmaf(xa[k], w, acc0[dc]);
                acc1[dc] = fmaf(xb[k], w, acc1[dc]);
            }
        }
    }

    const int t1 = tstart + tid;
    const int t2 = t1 + 128;
#pragma unroll
    for (int g = 0; g < 4; g++) {
        if (t1 < 500) {
            float4 o1;
            o1.x = selu_f(acc0[g * 4 + 0]); o1.y = selu_f(acc0[g * 4 + 1]);
            o1.z = selu_f(acc0[g * 4 + 2]); o1.w = selu_f(acc0[g * 4 + 3]);
            *reinterpret_cast<float4*>(qout + ((size_t)(b * 500 + t1)) * 128 + dg * 16 + g * 4) = o1;
        }
        if (t2 < 500) {
            float4 o2;
            o2.x = selu_f(acc1[g * 4 + 0]); o2.y = selu_f(acc1[g * 4 + 1]);
            o2.z = selu_f(acc1[g * 4 + 2]); o2.w = selu_f(acc1[g * 4 + 3]);
            *reinterpret_cast<float4*>(qout + ((size_t)(b * 500 + t2)) * 128 + dg * 16 + g * 4) = o2;
        }
    }
}

// ---------------------------------------------------------------------------
// mma.sync fused layer kernel v2. grid (C=128, B=8), 256 threads (8 warps).
// Precomputed packed bf16 hi/lo pair arrays (A frags = 3 LDS.32).
// Epilogue: 4 threads per t, 2 complete heads each, 2-shfl reduction.
// ---------------------------------------------------------------------------
#define DSTRIDE 268
#define SMEM_BYTES 75648

__global__ __launch_bounds__(256, 2)
void layer_mma_kernel(const float* __restrict__ xin,
                      const float* __restrict__ qT,
                      const float* __restrict__ wk,
                      const float* __restrict__ wv,
                      const float* __restrict__ wproj,
                      float* __restrict__ xout) {
    extern __shared__ char smem_raw[];
    float*    Dsm = reinterpret_cast<float*>(smem_raw);            // 64 x 268
    float*    xs  = reinterpret_cast<float*>(smem_raw + 68608);    // 544
    uint32_t* xh2 = reinterpret_cast<uint32_t*>(smem_raw + 70784); // 544
    uint32_t* xl2 = reinterpret_cast<uint32_t*>(smem_raw + 72960); // 544
    float*    wps = reinterpret_cast<float*>(smem_raw + 75136);    // 128

    const int c = blockIdx.x, b = blockIdx.y, tid = threadIdx.x;
    const int wid = tid >> 5, lane = tid & 31;
    const int g = lane >> 2, tg = lane & 3;

    const float* xrow = xin + (b * 128 + c) * 500;
    for (int i = tid; i < 544; i += 256) {
        int gg = i - 4;
        xs[i] = (gg >= 0 && gg < 500) ? xrow[gg] : 0.0f;
    }
    if (tid < 128) wps[tid] = wproj[c * 128 + tid];

    // B fragments (hi/lo) for this warp's 4 n-tiles, built from gmem
    const int slab = (wid & 3) * 32;
    const int colbase = ((wid < 4) ? 0 : 128) + slab;
    const float* wsrc = ((wid < 4) ? wk : wv) + c * 1152;
    uint32_t bh[4][2], bl[4][2];
#pragma unroll
    for (int nt = 0; nt < 4; nt++) {
        const float* wr = wsrc + (slab + nt * 8 + g) * 9;
        packhl(wr[2 * tg] * LOG2E, wr[2 * tg + 1] * LOG2E, bh[nt][0], bl[nt][0]);
        if (tg == 0) {
            packhl(wr[8] * LOG2E, 0.0f, bh[nt][1], bl[nt][1]);
        } else {
            bh[nt][1] = 0u; bl[nt][1] = 0u;
        }
    }
    __syncthreads();

    // packed bf16 hi/lo pair arrays: xh2[i] = {bf(x[i]), bf(x[i+1])}
    for (int i = tid; i < 540; i += 256) {
        uint32_t h, l;
        packhl(xs[i], xs[i + 1], h, l);
        xh2[i] = h; xl2[i] = l;
    }
    __syncthreads();

    const int tl = wid * 8 + (lane >> 2);   // epilogue: t within chunk
    const int part = lane & 3;              // quarter: 2 heads

#pragma unroll 1
    for (int chunk = 0; chunk < 8; chunk++) {
        const int t0c = (chunk < 7) ? chunk * 64 : 436;

        // ---- MMA phase: D[t0c + 0..63][0..255] ----
#pragma unroll 1
        for (int mt = 0; mt < 4; mt++) {
            const int r0 = t0c + mt * 16 + g;
            uint32_t ah[4], al[4];
            ah[0] = xh2[r0 + 2 * tg];       al[0] = xl2[r0 + 2 * tg];
            ah[1] = xh2[r0 + 8 + 2 * tg];   al[1] = xl2[r0 + 8 + 2 * tg];
            ah[2] = ah[1];                  al[2] = al[1];
            ah[3] = xh2[r0 + 16 + 2 * tg];  al[3] = xl2[r0 + 16 + 2 * tg];

#pragma unroll
            for (int nt = 0; nt < 4; nt++) {
                float cf[4] = {0.f, 0.f, 0.f, 0.f};
                float cc[4] = {0.f, 0.f, 0.f, 0.f};
                mma_bf16(cf, ah, bh[nt]);
                mma_bf16(cc, ah, bl[nt]);
                mma_bf16(cc, al, bh[nt]);
                float* d0 = &Dsm[(mt * 16 + g) * DSTRIDE + colbase + nt * 8 + 2 * tg];
                *reinterpret_cast<float2*>(d0) =
                    make_float2(cf[0] + cc[0], cf[1] + cc[1]);
                *reinterpret_cast<float2*>(d0 + 8 * DSTRIDE) =
                    make_float2(cf[2] + cc[2], cf[3] + cc[3]);
            }
        }
        __syncthreads();

        // ---- Epilogue: 4 threads per t, 2 complete heads each ----
        {
            const int t_glob = t0c + tl;
            const float* qrow = qT + ((size_t)(b * 500 + t_glob)) * 128 + part * 32;
            const float* dK = &Dsm[tl * DSTRIDE + part * 32];
            const float* dV = &Dsm[tl * DSTRIDE + 128 + part * 32];
            const float* wp = &wps[part * 32];

            float contrib = 0.0f;
#pragma unroll
            for (int h = 0; h < 2; h++) {
                float qk = 0.f, pv = 0.f;
#pragma unroll
                for (int i = 0; i < 4; i++) {
                    float4 d4 = *reinterpret_cast<const float4*>(dK + h * 16 + 4 * i);
                    float4 q4 = *reinterpret_cast<const float4*>(qrow + h * 16 + 4 * i);
                    qk = fmaf(q4.x, selu_s(d4.x), qk);
                    qk = fmaf(q4.y, selu_s(d4.y), qk);
                    qk = fmaf(q4.z, selu_s(d4.z), qk);
                    qk = fmaf(q4.w, selu_s(d4.w), qk);
                    float4 v4 = *reinterpret_cast<const float4*>(dV + h * 16 + 4 * i);
                    float4 w4 = *reinterpret_cast<const float4*>(wp + h * 16 + 4 * i);
                    pv = fmaf(w4.x, selu_s(v4.x), pv);
                    pv = fmaf(w4.y, selu_s(v4.y), pv);
                    pv = fmaf(w4.z, selu_s(v4.z), pv);
                    pv = fmaf(w4.w, selu_s(v4.w), pv);
                }
                contrib = fmaf(selu_s(Q_SC * qk), pv, contrib);
            }
            contrib += __shfl_xor_sync(0xffffffffu, contrib, 1);
            contrib += __shfl_xor_sync(0xffffffffu, contrib, 2);

            if (part == 0) {
                xout[(b * 128 + c) * 500 + t_glob] =
                    (xs[t_glob + 4] + selu_f(contrib)) * RES_SC;
            }
        }
        __syncthreads();
    }
}

// ---------------------------------------------------------------------------
// Head
// ---------------------------------------------------------------------------
__global__ __launch_bounds__(256)
void head_kernel(const float* __restrict__ x, const float* __restrict__ wh,
                 const float* __restrict__ bh, float* __restrict__ out) {
    const int n = blockIdx.x, b = blockIdx.y, tid = threadIdx.x;
    const float4* xr = reinterpret_cast<const float4*>(x + (size_t)b * 64000);
    const float4* wr = reinterpret_cast<const float4*>(wh + (size_t)n * 64000);
    float sum = 0.0f;
    for (int i = tid; i < 16000; i += 256) {
        float4 a = xr[i], w = wr[i];
        sum += a.x * w.x + a.y * w.y + a.z * w.z + a.w * w.w;
    }
#pragma unroll
    for (int off = 16; off; off >>= 1)
        sum += __shfl_down_sync(0xffffffffu, sum, off);
    __shared__ float ps[8];
    if ((tid & 31) == 0) ps[tid >> 5] = sum;
    __syncthreads();
    if (tid < 8) {
        sum = ps[tid];
#pragma unroll
        for (int off = 4; off; off >>= 1)
            sum += __shfl_down_sync(0xffu, sum, off);
        if (tid == 0) out[b * 40 + n] = sum + bh[n];
    }
}

// ---------------------------------------------------------------------------
extern "C" void kernel_launch(void* const* d_in, const int* in_sizes, int n_in,
                              void* d_out, int out_size) {
    const float* x     = (const float*)d_in[0];
    const float* wq    = (const float*)d_in[2];  // (2,128,21,9)
    const float* wk    = (const float*)d_in[3];  // (2,16384,1,9)
    const float* wv    = (const float*)d_in[4];  // (2,16384,1,9)
    const float* wproj = (const float*)d_in[5];  // (2,128,128)
    const float* whead = (const float*)d_in[6];  // (40,64000)
    const float* bhead = (const float*)d_in[7];  // (40,)
    float* out = (float*)d_out;

    float *gx = nullptr, *gq = nullptr;
    cudaGetSymbolAddress((void**)&gx, g_x);
    cudaGetSymbolAddress((void**)&gq, g_q);

    cudaFuncSetAttribute(layer_mma_kernel,
                         cudaFuncAttributeMaxDynamicSharedMemorySize, SMEM_BYTES);

    dim3 qg(8, 2, 8);
    dim3 lg(128, 8);
    dim3 hg(40, 8);

    q_kernel<<<qg, 128>>>(x, wq, gq);
    layer_mma_kernel<<<lg, 256, SMEM_BYTES>>>(x, gq, wk, wv, wproj, gx);
    q_kernel<<<qg, 128>>>(gx, wq + 24192, gq);
    layer_mma_kernel<<<lg, 256, SMEM_BYTES>>>(gx, gq, wk + 147456, wv + 147456,
                                              wproj + 16384, gx);
    head_kernel<<<hg, 256>>>(gx, whead, bhead, out);
}

// round 13
// speedup vs baseline: 1.5727x; 1.5727x over previous
#include <cuda_runtime.h>
#include <cuda_bf16.h>
#include <cstdint>

#define SELU_SC 1.0507009873554805f
#define SELU_AL 1.6732632423543772f
#define SELU_SA (SELU_SC * SELU_AL)
#define RES_SC  0.70710678118654752440f
#define LOG2E   1.4426950408889634f
#define LN2     0.6931471805599453f
#define SC_LN2  (SELU_SC * LN2)
#define Q_SC    (0.25f * LOG2E)

__device__ __forceinline__ float selu_f(float v) {
    float p = fmaxf(v, 0.0f);
    float m = fminf(v, 0.0f);
    float e = __expf(m);
    return fmaf(SELU_SA, e, fmaf(SELU_SC, p, -SELU_SA));
}
// selu on input pre-scaled by log2e
__device__ __forceinline__ float selu_s(float s) {
    float p = fmaxf(s, 0.0f);
    float m = fminf(s, 0.0f);
    float e;
    asm("ex2.approx.ftz.f32 %0, %1;" : "=f"(e) : "f"(m));
    return fmaf(SELU_SA, e, fmaf(SC_LN2, p, -SELU_SA));
}

__constant__ int c_occ[21] = {65,66,67,68,69,70,71,72,73,74,75,76,77,
                              81,82,83,84,88,89,90,94};

__device__ float g_x[8 * 128 * 500];
__device__ float g_q[8 * 500 * 128];   // transposed: [b][t][dd]

// hi/lo bf16 split pack: hi = {b(a), b(b)}, lo = residuals
__device__ __forceinline__ void packhl(float a, float b, uint32_t& hi, uint32_t& lo) {
    __nv_bfloat16 ha = __float2bfloat16(a), hb = __float2bfloat16(b);
    float ra = a - __bfloat162float(ha);
    float rb = b - __bfloat162float(hb);
    __nv_bfloat16 la = __float2bfloat16(ra), lb = __float2bfloat16(rb);
    uint16_t ua = *reinterpret_cast<uint16_t*>(&ha);
    uint16_t ub = *reinterpret_cast<uint16_t*>(&hb);
    uint16_t va = *reinterpret_cast<uint16_t*>(&la);
    uint16_t vb = *reinterpret_cast<uint16_t*>(&lb);
    hi = ((uint32_t)ub << 16) | ua;
    lo = ((uint32_t)vb << 16) | va;
}

__device__ __forceinline__ void mma_bf16(float c[4], const uint32_t a[4],
                                         const uint32_t b[2]) {
    asm volatile(
        "mma.sync.aligned.m16n8k16.row.col.f32.bf16.bf16.f32 "
        "{%0,%1,%2,%3}, {%4,%5,%6,%7}, {%8,%9}, {%0,%1,%2,%3};"
        : "+f"(c[0]), "+f"(c[1]), "+f"(c[2]), "+f"(c[3])
        : "r"(a[0]), "r"(a[1]), "r"(a[2]), "r"(a[3]), "r"(b[0]), "r"(b[1]));
}

// ---------------------------------------------------------------------------
// Q kernel — writes Q TRANSPOSED: qout[b][t][dd]
// ---------------------------------------------------------------------------
__global__ __launch_bounds__(128)
void q_kernel(const float* __restrict__ x, const float* __restrict__ wq,
              float* __restrict__ qout) {
    const int dg = blockIdx.x;
    const int tstart = blockIdx.y * 256;
    const int b = blockIdx.z;
    const int tid = threadIdx.x;

    __shared__ float xo[21 * 264];
    __shared__ float ws[16 * 189];

    for (int i = tid; i < 21 * 264; i += 128) {
        int o = i / 264, tt = i % 264;
        int g = tstart + tt - 4;
        xo[i] = (g >= 0 && g < 500) ? x[(b * 128 + c_occ[o]) * 500 + g] : 0.0f;
    }
    for (int i = tid; i < 16 * 189; i += 128)
        ws[i] = wq[dg * 16 * 189 + i];
    __syncthreads();

    float acc0[16], acc1[16];
#pragma unroll
    for (int i = 0; i < 16; i++) { acc0[i] = 0.0f; acc1[i] = 0.0f; }

#pragma unroll 1
    for (int o = 0; o < 21; o++) {
        float xa[9], xb[9];
#pragma unroll
        for (int k = 0; k < 9; k++) {
            xa[k] = xo[o * 264 + tid + k];
            xb[k] = xo[o * 264 + tid + 128 + k];
        }
#pragma unroll
        for (int dc = 0; dc < 16; dc++) {
#pragma unroll
            for (int k = 0; k < 9; k++) {
                float w = ws[dc * 189 + o * 9 + k];
                acc0[dc] = fmaf(xa[k], w, acc0[dc]);
                acc1[dc] = fmaf(xb[k], w, acc1[dc]);
            }
        }
    }

    const int t1 = tstart + tid;
    const int t2 = t1 + 128;
#pragma unroll
    for (int g = 0; g < 4; g++) {
        if (t1 < 500) {
            float4 o1;
            o1.x = selu_f(acc0[g * 4 + 0]); o1.y = selu_f(acc0[g * 4 + 1]);
            o1.z = selu_f(acc0[g * 4 + 2]); o1.w = selu_f(acc0[g * 4 + 3]);
            *reinterpret_cast<float4*>(qout + ((size_t)(b * 500 + t1)) * 128 + dg * 16 + g * 4) = o1;
        }
        if (t2 < 500) {
            float4 o2;
            o2.x = selu_f(acc1[g * 4 + 0]); o2.y = selu_f(acc1[g * 4 + 1]);
            o2.z = selu_f(acc1[g * 4 + 2]); o2.w = selu_f(acc1[g * 4 + 3]);
            *reinterpret_cast<float4*>(qout + ((size_t)(b * 500 + t2)) * 128 + dg * 16 + g * 4) = o2;
        }
    }
}

// ---------------------------------------------------------------------------
// mma.sync fused layer kernel v3. grid (C=128, B=8), 256 threads (8 warps).
//  - Precomputed packed bf16 hi/lo pair arrays -> A frags = 3 LDS.32 (R12)
//  - Parallel 2-accumulator MMA (no serial 3-chain) (R12)
//  - Warp-per-t conflict-free epilogue (R11)
// ---------------------------------------------------------------------------
#define DSTRIDE 268
#define SMEM_BYTES 75648

__global__ __launch_bounds__(256)
void layer_mma_kernel(const float* __restrict__ xin,
                      const float* __restrict__ qT,
                      const float* __restrict__ wk,
                      const float* __restrict__ wv,
                      const float* __restrict__ wproj,
                      float* __restrict__ xout) {
    extern __shared__ char smem_raw[];
    float*    Dsm = reinterpret_cast<float*>(smem_raw);            // 64 x 268
    float*    xs  = reinterpret_cast<float*>(smem_raw + 68608);    // 544
    uint32_t* xh2 = reinterpret_cast<uint32_t*>(smem_raw + 70784); // 544
    uint32_t* xl2 = reinterpret_cast<uint32_t*>(smem_raw + 72960); // 544
    float*    wps = reinterpret_cast<float*>(smem_raw + 75136);    // 128

    const int c = blockIdx.x, b = blockIdx.y, tid = threadIdx.x;
    const int wid = tid >> 5, lane = tid & 31;
    const int g = lane >> 2, tg = lane & 3;

    const float* xrow = xin + (b * 128 + c) * 500;
    for (int i = tid; i < 544; i += 256) {
        int gg = i - 4;
        xs[i] = (gg >= 0 && gg < 500) ? xrow[gg] : 0.0f;
    }
    if (tid < 128) wps[tid] = wproj[c * 128 + tid];

    // B fragments (hi/lo) for this warp's 4 n-tiles, built from gmem
    const int slab = (wid & 3) * 32;
    const int colbase = ((wid < 4) ? 0 : 128) + slab;
    const float* wsrc = ((wid < 4) ? wk : wv) + c * 1152;
    uint32_t bh[4][2], bl[4][2];
#pragma unroll
    for (int nt = 0; nt < 4; nt++) {
        const float* wr = wsrc + (slab + nt * 8 + g) * 9;
        packhl(wr[2 * tg] * LOG2E, wr[2 * tg + 1] * LOG2E, bh[nt][0], bl[nt][0]);
        if (tg == 0) {
            packhl(wr[8] * LOG2E, 0.0f, bh[nt][1], bl[nt][1]);
        } else {
            bh[nt][1] = 0u; bl[nt][1] = 0u;
        }
    }
    __syncthreads();

    // packed bf16 hi/lo pair arrays: xh2[i] = {bf(x[i]), bf(x[i+1])}
    for (int i = tid; i < 540; i += 256) {
        uint32_t h, l;
        packhl(xs[i], xs[i + 1], h, l);
        xh2[i] = h; xl2[i] = l;
    }
    __syncthreads();

#pragma unroll 1
    for (int chunk = 0; chunk < 8; chunk++) {
        const int t0c = (chunk < 7) ? chunk * 64 : 436;

        // ---- MMA phase: D[t0c + 0..63][0..255] ----
#pragma unroll 1
        for (int mt = 0; mt < 4; mt++) {
            const int r0 = t0c + mt * 16 + g;
            uint32_t ah[4], al[4];
            ah[0] = xh2[r0 + 2 * tg];       al[0] = xl2[r0 + 2 * tg];
            ah[1] = xh2[r0 + 8 + 2 * tg];   al[1] = xl2[r0 + 8 + 2 * tg];
            ah[2] = ah[1];                  al[2] = al[1];   // conv aliasing
            ah[3] = xh2[r0 + 16 + 2 * tg];  al[3] = xl2[r0 + 16 + 2 * tg];

#pragma unroll
            for (int nt = 0; nt < 4; nt++) {
                float cf[4] = {0.f, 0.f, 0.f, 0.f};
                float cc[4] = {0.f, 0.f, 0.f, 0.f};
                mma_bf16(cf, ah, bh[nt]);
                mma_bf16(cc, ah, bl[nt]);
                mma_bf16(cc, al, bh[nt]);
                float* d0 = &Dsm[(mt * 16 + g) * DSTRIDE + colbase + nt * 8 + 2 * tg];
                *reinterpret_cast<float2*>(d0) =
                    make_float2(cf[0] + cc[0], cf[1] + cc[1]);
                *reinterpret_cast<float2*>(d0 + 8 * DSTRIDE) =
                    make_float2(cf[2] + cc[2], cf[3] + cc[3]);
            }
        }
        __syncthreads();

        // ---- Epilogue (R11): warp handles t rows wid, wid+8, ... ----
#pragma unroll 1
        for (int i = 0; i < 8; i++) {
            const int tl = wid + i * 8;
            const int t_glob = t0c + tl;

            float4 dk = *reinterpret_cast<const float4*>(&Dsm[tl * DSTRIDE + lane * 4]);
            float4 q4 = *reinterpret_cast<const float4*>(
                qT + ((size_t)(b * 500 + t_glob)) * 128 + lane * 4);
            float qk = q4.x * selu_s(dk.x);
            qk = fmaf(q4.y, selu_s(dk.y), qk);
            qk = fmaf(q4.z, selu_s(dk.z), qk);
            qk = fmaf(q4.w, selu_s(dk.w), qk);
            qk += __shfl_xor_sync(0xffffffffu, qk, 1);
            qk += __shfl_xor_sync(0xffffffffu, qk, 2);
            float gate = selu_s(Q_SC * qk);

            float4 dv = *reinterpret_cast<const float4*>(&Dsm[tl * DSTRIDE + 128 + lane * 4]);
            float4 w4 = *reinterpret_cast<const float4*>(&wps[lane * 4]);
            float pv = w4.x * selu_s(dv.x);
            pv = fmaf(w4.y, selu_s(dv.y), pv);
            pv = fmaf(w4.z, selu_s(dv.z), pv);
            pv = fmaf(w4.w, selu_s(dv.w), pv);

            float contrib = gate * pv;
#pragma unroll
            for (int off = 16; off; off >>= 1)
                contrib += __shfl_xor_sync(0xffffffffu, contrib, off);

            if (lane == 0) {
                xout[(b * 128 + c) * 500 + t_glob] =
                    (xs[t_glob + 4] + selu_f(contrib)) * RES_SC;
            }
        }
        __syncthreads();
    }
}

// ---------------------------------------------------------------------------
// Head
// ---------------------------------------------------------------------------
__global__ __launch_bounds__(256)
void head_kernel(const float* __restrict__ x, const float* __restrict__ wh,
                 const float* __restrict__ bh, float* __restrict__ out) {
    const int n = blockIdx.x, b = blockIdx.y, tid = threadIdx.x;
    const float4* xr = reinterpret_cast<const float4*>(x + (size_t)b * 64000);
    const float4* wr = reinterpret_cast<const float4*>(wh + (size_t)n * 64000);
    float sum = 0.0f;
    for (int i = tid; i < 16000; i += 256) {
        float4 a = xr[i], w = wr[i];
        sum += a.x * w.x + a.y * w.y + a.z * w.z + a.w * w.w;
    }
#pragma unroll
    for (int off = 16; off; off >>= 1)
        sum += __shfl_down_sync(0xffffffffu, sum, off);
    __shared__ float ps[8];
    if ((tid & 31) == 0) ps[tid >> 5] = sum;
    __syncthreads();
    if (tid < 8) {
        sum = ps[tid];
#pragma unroll
        for (int off = 4; off; off >>= 1)
            sum += __shfl_down_sync(0xffu, sum, off);
        if (tid == 0) out[b * 40 + n] = sum + bh[n];
    }
}

// ---------------------------------------------------------------------------
extern "C" void kernel_launch(void* const* d_in, const int* in_sizes, int n_in,
                              void* d_out, int out_size) {
    const float* x     = (const float*)d_in[0];
    const float* wq    = (const float*)d_in[2];  // (2,128,21,9)
    const float* wk    = (const float*)d_in[3];  // (2,16384,1,9)
    const float* wv    = (const float*)d_in[4];  // (2,16384,1,9)
    const float* wproj = (const float*)d_in[5];  // (2,128,128)
    const float* whead = (const float*)d_in[6];  // (40,64000)
    const float* bhead = (const float*)d_in[7];  // (40,)
    float* out = (float*)d_out;

    float *gx = nullptr, *gq = nullptr;
    cudaGetSymbolAddress((void**)&gx, g_x);
    cudaGetSymbolAddress((void**)&gq, g_q);

    cudaFuncSetAttribute(layer_mma_kernel,
                         cudaFuncAttributeMaxDynamicSharedMemorySize, SMEM_BYTES);

    dim3 qg(8, 2, 8);
    dim3 lg(128, 8);
    dim3 hg(40, 8);

    q_kernel<<<qg, 128>>>(x, wq, gq);
    layer_mma_kernel<<<lg, 256, SMEM_BYTES>>>(x, gq, wk, wv, wproj, gx);
    q_kernel<<<qg, 128>>>(gx, wq + 24192, gq);
    layer_mma_kernel<<<lg, 256, SMEM_BYTES>>>(gx, gq, wk + 147456, wv + 147456,
                                              wproj + 16384, gx);
    head_kernel<<<hg, 256>>>(gx, whead, bhead, out);
}

// round 14
// speedup vs baseline: 2.2772x; 1.4479x over previous
#include <cuda_runtime.h>

#define SELU_SC 1.0507009873554805f
#define SELU_AL 1.6732632423543772f
#define SELU_SA (SELU_SC * SELU_AL)
#define RES_SC  0.70710678118654752440f
#define LOG2E   1.4426950408889634f
#define LN2     0.6931471805599453f
#define SC_LN2  (SELU_SC * LN2)
#define Q_SC    (0.25f * LOG2E)

// standard branch-free selu (for unscaled inputs)
__device__ __forceinline__ float selu_f(float v) {
    float p = fmaxf(v, 0.0f);
    float m = fminf(v, 0.0f);
    float e = __expf(m);
    return fmaf(SELU_SA, e, fmaf(SELU_SC, p, -SELU_SA));
}

// selu on pre-scaled input s = v*log2e  (weights pre-multiplied by log2e)
__device__ __forceinline__ float selu_s(float s) {
    float p = fmaxf(s, 0.0f);
    float m = fminf(s, 0.0f);
    float e;
    asm("ex2.approx.ftz.f32 %0, %1;" : "=f"(e) : "f"(m));
    return fmaf(SELU_SA, e, fmaf(SC_LN2, p, -SELU_SA));
}

__constant__ int c_occ[21] = {65,66,67,68,69,70,71,72,73,74,75,76,77,
                              81,82,83,84,88,89,90,94};

// scratch (no cudaMalloc allowed)
__device__ float g_x[8 * 128 * 500];
__device__ float g_q[8 * 128 * 500];

// ---------------------------------------------------------------------------
// Q kernel v2: grid (16 dch-groups of 8, 4 t-tiles of 128, 8 b), 128 threads.
// Each thread: one t, 8 dch. Output layout [b][dch][t] (as R9 layer expects).
// ---------------------------------------------------------------------------
__global__ __launch_bounds__(128)
void q_kernel(const float* __restrict__ x, const float* __restrict__ wq,
              float* __restrict__ qout) {
    const int dg = blockIdx.x;            // 8-dch group
    const int tstart = blockIdx.y * 128;  // t tile
    const int b = blockIdx.z;
    const int tid = threadIdx.x;

    __shared__ float xo[21 * 136];
    __shared__ float ws[8 * 189];

    for (int i = tid; i < 21 * 136; i += 128) {
        int o = i / 136, tt = i % 136;
        int g = tstart + tt - 4;
        xo[i] = (g >= 0 && g < 500) ? x[(b * 128 + c_occ[o]) * 500 + g] : 0.0f;
    }
    for (int i = tid; i < 8 * 189; i += 128)
        ws[i] = wq[dg * 8 * 189 + i];
    __syncthreads();

    const int t = tstart + tid;
    if (t >= 500) return;

    float acc[8];
#pragma unroll
    for (int i = 0; i < 8; i++) acc[i] = 0.0f;

#pragma unroll 1
    for (int o = 0; o < 21; o++) {
        float xa[9];
#pragma unroll
        for (int k = 0; k < 9; k++)
            xa[k] = xo[o * 136 + tid + k];
#pragma unroll
        for (int dc = 0; dc < 8; dc++) {
#pragma unroll
            for (int k = 0; k < 9; k++) {
                float w = ws[dc * 189 + o * 9 + k];
                acc[dc] = fmaf(xa[k], w, acc[dc]);
            }
        }
    }

#pragma unroll
    for (int dc = 0; dc < 8; dc++)
        qout[(b * 128 + dg * 8 + dc) * 500 + t] = selu_f(acc[dc]);
}

// ---------------------------------------------------------------------------
// Fused layer kernel — EXACT R9 structure (proven 88.4 us/layer).
// grid (C=128, B=8), 256 threads.
//   tt = tid & 127 : t-chunk (4 consecutive t, 125 active)
//   hh = tid >> 7  : head half (heads hh*4 .. hh*4+3)
// wks row (12 floats): [k0..k7][k8, wp, v8, pad]  -> kc4 = LDS.128
// ---------------------------------------------------------------------------
__global__ __launch_bounds__(256)
void layer_kernel(const float* __restrict__ xin,
                  const float* __restrict__ q,
                  const float* __restrict__ wk,
                  const float* __restrict__ wv,
                  const float* __restrict__ wproj,
                  float* __restrict__ xout) {
    const int c = blockIdx.x, b = blockIdx.y, tid = threadIdx.x;
    const int tt = tid & 127;
    const int hh = tid >> 7;

    __shared__ __align__(16) float xs[508];       // x row padded by 4 each side
    __shared__ __align__(16) float wks[128 * 12]; // K w ×log2e + {k8,wp,v8}
    __shared__ __align__(16) float wvs[128 * 12]; // V w ×log2e (first 8)
    __shared__ __align__(16) float pacc[125 * 4]; // partial acc from half 1

    const float* xrow = xin + (b * 128 + c) * 500;
    for (int i = tid; i < 508; i += 256) {
        int g = i - 4;
        xs[i] = (g >= 0 && g < 500) ? xrow[g] : 0.0f;
    }
    const float* wkr = wk + c * 1152;
    const float* wvr = wv + c * 1152;
    for (int i = tid; i < 1152; i += 256) {
        int row = i / 9, kk = i - row * 9;
        wks[row * 12 + kk] = wkr[i] * LOG2E;
        float wvv = wvr[i] * LOG2E;
        if (kk < 8) wvs[row * 12 + kk] = wvv;
        else        wks[row * 12 + 10] = wvv;     // v8 slot
    }
    if (tid < 128) wks[tid * 12 + 9] = wproj[c * 128 + tid];
    __syncthreads();

    const bool active = (tt < 125);
    const int t0 = tt * 4;
    float acc[4] = {0.f, 0.f, 0.f, 0.f};
    float xw[12];

    if (active) {
#pragma unroll
        for (int i = 0; i < 12; i++) xw[i] = xs[t0 + i];

        const float* qbase = q + (size_t)(b * 128 + hh * 64) * 500 + t0;
        const int d0 = hh * 64;

#pragma unroll 1
        for (int h = 0; h < 4; h++) {
            float qk[4] = {0.f, 0.f, 0.f, 0.f};
            float pv[4] = {0.f, 0.f, 0.f, 0.f};
#pragma unroll 4
            for (int j = 0; j < 16; j++) {
                const int dd = d0 + h * 16 + j;
                const float* krow = &wks[dd * 12];
                const float* vrow = &wvs[dd * 12];

                float4 ka  = *reinterpret_cast<const float4*>(krow);
                float4 kb  = *reinterpret_cast<const float4*>(krow + 4);
                float4 kc4 = *reinterpret_cast<const float4*>(krow + 8); // {k8,wp,v8,-}
                float4 va  = *reinterpret_cast<const float4*>(vrow);
                float4 vb  = *reinterpret_cast<const float4*>(vrow + 4);

                float kk[4], vv[4];
#pragma unroll
                for (int u = 0; u < 4; u++) {
                    float k0 = ka.x * xw[u];
                    float v0 = va.x * xw[u];
                    k0 = fmaf(ka.y, xw[u + 1], k0);  v0 = fmaf(va.y, xw[u + 1], v0);
                    k0 = fmaf(ka.z, xw[u + 2], k0);  v0 = fmaf(va.z, xw[u + 2], v0);
                    k0 = fmaf(ka.w, xw[u + 3], k0);  v0 = fmaf(va.w, xw[u + 3], v0);
                    k0 = fmaf(kb.x, xw[u + 4], k0);  v0 = fmaf(vb.x, xw[u + 4], v0);
                    k0 = fmaf(kb.y, xw[u + 5], k0);  v0 = fmaf(vb.y, xw[u + 5], v0);
                    k0 = fmaf(kb.z, xw[u + 6], k0);  v0 = fmaf(vb.z, xw[u + 6], v0);
                    k0 = fmaf(kb.w, xw[u + 7], k0);  v0 = fmaf(vb.w, xw[u + 7], v0);
                    k0 = fmaf(kc4.x, xw[u + 8], k0); v0 = fmaf(kc4.z, xw[u + 8], v0);
                    kk[u] = k0; vv[u] = v0;
                }

                float4 qv = *reinterpret_cast<const float4*>(qbase + (h * 16 + j) * 500);
                qk[0] = fmaf(qv.x, selu_s(kk[0]), qk[0]);
                qk[1] = fmaf(qv.y, selu_s(kk[1]), qk[1]);
                qk[2] = fmaf(qv.z, selu_s(kk[2]), qk[2]);
                qk[3] = fmaf(qv.w, selu_s(kk[3]), qk[3]);

                float wp = kc4.y;
#pragma unroll
                for (int u = 0; u < 4; u++)
                    pv[u] = fmaf(wp, selu_s(vv[u]), pv[u]);
            }
#pragma unroll
            for (int u = 0; u < 4; u++) {
                float gate = selu_s(Q_SC * qk[u]);   // selu(0.25*qk)
                acc[u] = fmaf(gate, pv[u], acc[u]);
            }
        }

        if (hh == 1) {
            float4 pa = make_float4(acc[0], acc[1], acc[2], acc[3]);
            *reinterpret_cast<float4*>(&pacc[tt * 4]) = pa;
        }
    }
    __syncthreads();

    if (active && hh == 0) {
        float4 pa = *reinterpret_cast<const float4*>(&pacc[tt * 4]);
        acc[0] += pa.x; acc[1] += pa.y; acc[2] += pa.z; acc[3] += pa.w;
        float4 res;
        res.x = (xw[4] + selu_f(acc[0])) * RES_SC;
        res.y = (xw[5] + selu_f(acc[1])) * RES_SC;
        res.z = (xw[6] + selu_f(acc[2])) * RES_SC;
        res.w = (xw[7] + selu_f(acc[3])) * RES_SC;
        *reinterpret_cast<float4*>(xout + (size_t)(b * 128 + c) * 500 + t0) = res;
    }
}

// ---------------------------------------------------------------------------
// Head v2: 4 heads per block; grid (10, 8), 256 threads.
// x slab read once per block per i (shared across the 4 heads).
// ---------------------------------------------------------------------------
__global__ __launch_bounds__(256)
void head_kernel(const float* __restrict__ x, const float* __restrict__ wh,
                 const float* __restrict__ bh, float* __restrict__ out) {
    const int n0 = blockIdx.x * 4, b = blockIdx.y, tid = threadIdx.x;
    const float4* xr = reinterpret_cast<const float4*>(x + (size_t)b * 64000);
    const float4* w0 = reinterpret_cast<const float4*>(wh + (size_t)(n0 + 0) * 64000);
    const float4* w1 = reinterpret_cast<const float4*>(wh + (size_t)(n0 + 1) * 64000);
    const float4* w2 = reinterpret_cast<const float4*>(wh + (size_t)(n0 + 2) * 64000);
    const float4* w3 = reinterpret_cast<const float4*>(wh + (size_t)(n0 + 3) * 64000);

    float s0 = 0.f, s1 = 0.f, s2 = 0.f, s3 = 0.f;
    for (int i = tid; i < 16000; i += 256) {
        float4 a = xr[i];
        float4 w = w0[i];
        s0 += a.x * w.x + a.y * w.y + a.z * w.z + a.w * w.w;
        w = w1[i];
        s1 += a.x * w.x + a.y * w.y + a.z * w.z + a.w * w.w;
        w = w2[i];
        s2 += a.x * w.x + a.y * w.y + a.z * w.z + a.w * w.w;
        w = w3[i];
        s3 += a.x * w.x + a.y * w.y + a.z * w.z + a.w * w.w;
    }
#pragma unroll
    for (int off = 16; off; off >>= 1) {
        s0 += __shfl_down_sync(0xffffffffu, s0, off);
        s1 += __shfl_down_sync(0xffffffffu, s1, off);
        s2 += __shfl_down_sync(0xffffffffu, s2, off);
        s3 += __shfl_down_sync(0xffffffffu, s3, off);
    }
    __shared__ float ps[8][4];
    if ((tid & 31) == 0) {
        int w = tid >> 5;
        ps[w][0] = s0; ps[w][1] = s1; ps[w][2] = s2; ps[w][3] = s3;
    }
    __syncthreads();
    if (tid < 4) {
        float sum = 0.f;
#pragma unroll
        for (int w = 0; w < 8; w++) sum += ps[w][tid];
        out[b * 40 + n0 + tid] = sum + bh[n0 + tid];
    }
}

// ---------------------------------------------------------------------------
extern "C" void kernel_launch(void* const* d_in, const int* in_sizes, int n_in,
                              void* d_out, int out_size) {
    const float* x     = (const float*)d_in[0];
    const float* wq    = (const float*)d_in[2];  // (2,128,21,9)
    const float* wk    = (const float*)d_in[3];  // (2,16384,1,9)
    const float* wv    = (const float*)d_in[4];  // (2,16384,1,9)
    const float* wproj = (const float*)d_in[5];  // (2,128,128)
    const float* whead = (const float*)d_in[6];  // (40,64000)
    const float* bhead = (const float*)d_in[7];  // (40,)
    float* out = (float*)d_out;

    float *gx = nullptr, *gq = nullptr;
    cudaGetSymbolAddress((void**)&gx, g_x);
    cudaGetSymbolAddress((void**)&gq, g_q);

    dim3 qg(16, 4, 8);
    dim3 lg(128, 8);
    dim3 hg(10, 8);

    q_kernel<<<qg, 128>>>(x, wq, gq);
    layer_kernel<<<lg, 256>>>(x, gq, wk, wv, wproj, gx);
    q_kernel<<<qg, 128>>>(gx, wq + 24192, gq);
    layer_kernel<<<lg, 256>>>(gx, gq, wk + 147456, wv + 147456,
                              wproj + 16384, gx);
    head_kernel<<<hg, 256>>>(gx, whead, bhead, out);
}

// round 15
// speedup vs baseline: 2.3469x; 1.0306x over previous
#include <cuda_runtime.h>

#define SELU_SC 1.0507009873554805f
#define SELU_AL 1.6732632423543772f
#define SELU_SA (SELU_SC * SELU_AL)
#define RES_SC  0.70710678118654752440f
#define LOG2E   1.4426950408889634f
#define LN2     0.6931471805599453f
#define SC_LN2  (SELU_SC * LN2)
#define Q_SC    (0.25f * LOG2E)

// standard branch-free selu (for unscaled inputs)
__device__ __forceinline__ float selu_f(float v) {
    float p = fmaxf(v, 0.0f);
    float m = fminf(v, 0.0f);
    float e = __expf(m);
    return fmaf(SELU_SA, e, fmaf(SELU_SC, p, -SELU_SA));
}

// selu on pre-scaled input s = v*log2e  (weights pre-multiplied by log2e)
__device__ __forceinline__ float selu_s(float s) {
    float p = fmaxf(s, 0.0f);
    float m = fminf(s, 0.0f);
    float e;
    asm("ex2.approx.ftz.f32 %0, %1;" : "=f"(e) : "f"(m));
    return fmaf(SELU_SA, e, fmaf(SC_LN2, p, -SELU_SA));
}

__constant__ int c_occ[21] = {65,66,67,68,69,70,71,72,73,74,75,76,77,
                              81,82,83,84,88,89,90,94};

// scratch (no cudaMalloc allowed)
__device__ float g_x[8 * 128 * 500];
__device__ float g_q[8 * 128 * 500];

// ---------------------------------------------------------------------------
// Q kernel v3: grid (8 dch-groups of 16, 4 t-tiles of 128, 8 b), 128 threads.
// Same 16-dch-per-thread structure as R9 (FMA/LDS ratio preserved), but 1 t
// per thread and 2x the blocks -> half the per-thread latency exposure.
// ---------------------------------------------------------------------------
__global__ __launch_bounds__(128)
void q_kernel(const float* __restrict__ x, const float* __restrict__ wq,
              float* __restrict__ qout) {
    const int dg = blockIdx.x;            // 16-dch group
    const int tstart = blockIdx.y * 128;  // t tile
    const int b = blockIdx.z;
    const int tid = threadIdx.x;

    __shared__ float xo[21 * 136];
    __shared__ float ws[16 * 189];

    for (int i = tid; i < 21 * 136; i += 128) {
        int o = i / 136, tt = i % 136;
        int g = tstart + tt - 4;
        xo[i] = (g >= 0 && g < 500) ? x[(b * 128 + c_occ[o]) * 500 + g] : 0.0f;
    }
    for (int i = tid; i < 16 * 189; i += 128)
        ws[i] = wq[dg * 16 * 189 + i];
    __syncthreads();

    const int t = tstart + tid;
    if (t >= 500) return;

    float acc[16];
#pragma unroll
    for (int i = 0; i < 16; i++) acc[i] = 0.0f;

#pragma unroll 1
    for (int o = 0; o < 21; o++) {
        float xa[9];
#pragma unroll
        for (int k = 0; k < 9; k++)
            xa[k] = xo[o * 136 + tid + k];
#pragma unroll
        for (int dc = 0; dc < 16; dc++) {
#pragma unroll
            for (int k = 0; k < 9; k++) {
                float w = ws[dc * 189 + o * 9 + k];
                acc[dc] = fmaf(xa[k], w, acc[dc]);
            }
        }
    }

#pragma unroll
    for (int dc = 0; dc < 16; dc++)
        qout[(b * 128 + dg * 16 + dc) * 500 + t] = selu_f(acc[dc]);
}

// ---------------------------------------------------------------------------
// Fused layer kernel — EXACT R9 structure (proven 88.4 us/layer).
// grid (C=128, B=8), 256 threads.
//   tt = tid & 127 : t-chunk (4 consecutive t, 125 active)
//   hh = tid >> 7  : head half (heads hh*4 .. hh*4+3)
// wks row (12 floats): [k0..k7][k8, wp, v8, pad]  -> kc4 = LDS.128
// ---------------------------------------------------------------------------
__global__ __launch_bounds__(256)
void layer_kernel(const float* __restrict__ xin,
                  const float* __restrict__ q,
                  const float* __restrict__ wk,
                  const float* __restrict__ wv,
                  const float* __restrict__ wproj,
                  float* __restrict__ xout) {
    const int c = blockIdx.x, b = blockIdx.y, tid = threadIdx.x;
    const int tt = tid & 127;
    const int hh = tid >> 7;

    __shared__ __align__(16) float xs[508];       // x row padded by 4 each side
    __shared__ __align__(16) float wks[128 * 12]; // K w ×log2e + {k8,wp,v8}
    __shared__ __align__(16) float wvs[128 * 12]; // V w ×log2e (first 8)
    __shared__ __align__(16) float pacc[125 * 4]; // partial acc from half 1

    const float* xrow = xin + (b * 128 + c) * 500;
    for (int i = tid; i < 508; i += 256) {
        int g = i - 4;
        xs[i] = (g >= 0 && g < 500) ? xrow[g] : 0.0f;
    }
    const float* wkr = wk + c * 1152;
    const float* wvr = wv + c * 1152;
    for (int i = tid; i < 1152; i += 256) {
        int row = i / 9, kk = i - row * 9;
        wks[row * 12 + kk] = wkr[i] * LOG2E;
        float wvv = wvr[i] * LOG2E;
        if (kk < 8) wvs[row * 12 + kk] = wvv;
        else        wks[row * 12 + 10] = wvv;     // v8 slot
    }
    if (tid < 128) wks[tid * 12 + 9] = wproj[c * 128 + tid];
    __syncthreads();

    const bool active = (tt < 125);
    const int t0 = tt * 4;
    float acc[4] = {0.f, 0.f, 0.f, 0.f};
    float xw[12];

    if (active) {
#pragma unroll
        for (int i = 0; i < 12; i++) xw[i] = xs[t0 + i];

        const float* qbase = q + (size_t)(b * 128 + hh * 64) * 500 + t0;
        const int d0 = hh * 64;

#pragma unroll 1
        for (int h = 0; h < 4; h++) {
            float qk[4] = {0.f, 0.f, 0.f, 0.f};
            float pv[4] = {0.f, 0.f, 0.f, 0.f};
#pragma unroll 4
            for (int j = 0; j < 16; j++) {
                const int dd = d0 + h * 16 + j;
                const float* krow = &wks[dd * 12];
                const float* vrow = &wvs[dd * 12];

                float4 ka  = *reinterpret_cast<const float4*>(krow);
                float4 kb  = *reinterpret_cast<const float4*>(krow + 4);
                float4 kc4 = *reinterpret_cast<const float4*>(krow + 8); // {k8,wp,v8,-}
                float4 va  = *reinterpret_cast<const float4*>(vrow);
                float4 vb  = *reinterpret_cast<const float4*>(vrow + 4);

                float kk[4], vv[4];
#pragma unroll
                for (int u = 0; u < 4; u++) {
                    float k0 = ka.x * xw[u];
                    float v0 = va.x * xw[u];
                    k0 = fmaf(ka.y, xw[u + 1], k0);  v0 = fmaf(va.y, xw[u + 1], v0);
                    k0 = fmaf(ka.z, xw[u + 2], k0);  v0 = fmaf(va.z, xw[u + 2], v0);
                    k0 = fmaf(ka.w, xw[u + 3], k0);  v0 = fmaf(va.w, xw[u + 3], v0);
                    k0 = fmaf(kb.x, xw[u + 4], k0);  v0 = fmaf(vb.x, xw[u + 4], v0);
                    k0 = fmaf(kb.y, xw[u + 5], k0);  v0 = fmaf(vb.y, xw[u + 5], v0);
                    k0 = fmaf(kb.z, xw[u + 6], k0);  v0 = fmaf(vb.z, xw[u + 6], v0);
                    k0 = fmaf(kb.w, xw[u + 7], k0);  v0 = fmaf(vb.w, xw[u + 7], v0);
                    k0 = fmaf(kc4.x, xw[u + 8], k0); v0 = fmaf(kc4.z, xw[u + 8], v0);
                    kk[u] = k0; vv[u] = v0;
                }

                float4 qv = *reinterpret_cast<const float4*>(qbase + (h * 16 + j) * 500);
                qk[0] = fmaf(qv.x, selu_s(kk[0]), qk[0]);
                qk[1] = fmaf(qv.y, selu_s(kk[1]), qk[1]);
                qk[2] = fmaf(qv.z, selu_s(kk[2]), qk[2]);
                qk[3] = fmaf(qv.w, selu_s(kk[3]), qk[3]);

                float wp = kc4.y;
#pragma unroll
                for (int u = 0; u < 4; u++)
                    pv[u] = fmaf(wp, selu_s(vv[u]), pv[u]);
            }
#pragma unroll
            for (int u = 0; u < 4; u++) {
                float gate = selu_s(Q_SC * qk[u]);   // selu(0.25*qk)
                acc[u] = fmaf(gate, pv[u], acc[u]);
            }
        }

        if (hh == 1) {
            float4 pa = make_float4(acc[0], acc[1], acc[2], acc[3]);
            *reinterpret_cast<float4*>(&pacc[tt * 4]) = pa;
        }
    }
    __syncthreads();

    if (active && hh == 0) {
        float4 pa = *reinterpret_cast<const float4*>(&pacc[tt * 4]);
        acc[0] += pa.x; acc[1] += pa.y; acc[2] += pa.z; acc[3] += pa.w;
        float4 res;
        res.x = (xw[4] + selu_f(acc[0])) * RES_SC;
        res.y = (xw[5] + selu_f(acc[1])) * RES_SC;
        res.z = (xw[6] + selu_f(acc[2])) * RES_SC;
        res.w = (xw[7] + selu_f(acc[3])) * RES_SC;
        *reinterpret_cast<float4*>(xout + (size_t)(b * 128 + c) * 500 + t0) = res;
    }
}

// ---------------------------------------------------------------------------
// Head v3: 2 heads per block; grid (20, 8), 256 threads (1280 warps total).
// Halves x-slab re-reads vs R9 while keeping ~8.6 warps/SM of MLP.
// ---------------------------------------------------------------------------
__global__ __launch_bounds__(256)
void head_kernel(const float* __restrict__ x, const float* __restrict__ wh,
                 const float* __restrict__ bh, float* __restrict__ out) {
    const int n0 = blockIdx.x * 2, b = blockIdx.y, tid = threadIdx.x;
    const float4* xr = reinterpret_cast<const float4*>(x + (size_t)b * 64000);
    const float4* w0 = reinterpret_cast<const float4*>(wh + (size_t)(n0 + 0) * 64000);
    const float4* w1 = reinterpret_cast<const float4*>(wh + (size_t)(n0 + 1) * 64000);

    float s0 = 0.f, s1 = 0.f;
    for (int i = tid; i < 16000; i += 256) {
        float4 a = xr[i];
        float4 w = w0[i];
        s0 += a.x * w.x + a.y * w.y + a.z * w.z + a.w * w.w;
        w = w1[i];
        s1 += a.x * w.x + a.y * w.y + a.z * w.z + a.w * w.w;
    }
#pragma unroll
    for (int off = 16; off; off >>= 1) {
        s0 += __shfl_down_sync(0xffffffffu, s0, off);
        s1 += __shfl_down_sync(0xffffffffu, s1, off);
    }
    __shared__ float ps[8][2];
    if ((tid & 31) == 0) {
        int w = tid >> 5;
        ps[w][0] = s0; ps[w][1] = s1;
    }
    __syncthreads();
    if (tid < 2) {
        float sum = 0.f;
#pragma unroll
        for (int w = 0; w < 8; w++) sum += ps[w][tid];
        out[b * 40 + n0 + tid] = sum + bh[n0 + tid];
    }
}

// ---------------------------------------------------------------------------
extern "C" void kernel_launch(void* const* d_in, const int* in_sizes, int n_in,
                              void* d_out, int out_size) {
    const float* x     = (const float*)d_in[0];
    const float* wq    = (const float*)d_in[2];  // (2,128,21,9)
    const float* wk    = (const float*)d_in[3];  // (2,16384,1,9)
    const float* wv    = (const float*)d_in[4];  // (2,16384,1,9)
    const float* wproj = (const float*)d_in[5];  // (2,128,128)
    const float* whead = (const float*)d_in[6];  // (40,64000)
    const float* bhead = (const float*)d_in[7];  // (40,)
    float* out = (float*)d_out;

    float *gx = nullptr, *gq = nullptr;
    cudaGetSymbolAddress((void**)&gx, g_x);
    cudaGetSymbolAddress((void**)&gq, g_q);

    dim3 qg(8, 4, 8);
    dim3 lg(128, 8);
    dim3 hg(20, 8);

    q_kernel<<<qg, 128>>>(x, wq, gq);
    layer_kernel<<<lg, 256>>>(x, gq, wk, wv, wproj, gx);
    q_kernel<<<qg, 128>>>(gx, wq + 24192, gq);
    layer_kernel<<<lg, 256>>>(gx, gq, wk + 147456, wv + 147456,
                              wproj + 16384, gx);
    head_kernel<<<hg, 256>>>(gx, whead, bhead, out);
}

// round 16
// speedup vs baseline: 2.6008x; 1.1082x over previous
#include <cuda_runtime.h>

#define SELU_SC 1.0507009873554805f
#define SELU_AL 1.6732632423543772f
#define SELU_SA (SELU_SC * SELU_AL)
#define RES_SC  0.70710678118654752440f
#define LOG2E   1.4426950408889634f
#define LN2     0.6931471805599453f
#define SC_LN2  (SELU_SC * LN2)
#define Q_SC    (0.25f * LOG2E)

// standard branch-free selu (for unscaled inputs)
__device__ __forceinline__ float selu_f(float v) {
    float p = fmaxf(v, 0.0f);
    float m = fminf(v, 0.0f);
    float e = __expf(m);
    return fmaf(SELU_SA, e, fmaf(SELU_SC, p, -SELU_SA));
}

// selu on pre-scaled input s = v*log2e  (weights pre-multiplied by log2e)
__device__ __forceinline__ float selu_s(float s) {
    float p = fmaxf(s, 0.0f);
    float m = fminf(s, 0.0f);
    float e;
    asm("ex2.approx.ftz.f32 %0, %1;" : "=f"(e) : "f"(m));
    return fmaf(SELU_SA, e, fmaf(SC_LN2, p, -SELU_SA));
}

__constant__ int c_occ[21] = {65,66,67,68,69,70,71,72,73,74,75,76,77,
                              81,82,83,84,88,89,90,94};

// scratch (no cudaMalloc allowed)
__device__ float g_x[8 * 128 * 500];
__device__ float g_q[8 * 128 * 500];

// ---------------------------------------------------------------------------
// Q kernel v4: R9 structure (grid (8 dg, 2 t-tiles of 256, 8 b), 128 threads,
// 2 t x 16 dch per thread) with weights re-laid into 12-float padded rows
// (x LOG2E) -> 2x LDS.128 + LDS.32 per 9-tap row instead of 9 scalar LDS.
// ---------------------------------------------------------------------------
__global__ __launch_bounds__(128)
void q_kernel(const float* __restrict__ x, const float* __restrict__ wq,
              float* __restrict__ qout) {
    const int dg = blockIdx.x;            // 16-dch group
    const int tstart = blockIdx.y * 256;  // t tile
    const int b = blockIdx.z;
    const int tid = threadIdx.x;

    __shared__ float xo[21 * 264];
    __shared__ __align__(16) float ws[16 * 21 * 12];  // padded weight rows

    for (int i = tid; i < 21 * 264; i += 128) {
        int o = i / 264, tt = i % 264;
        int g = tstart + tt - 4;
        xo[i] = (g >= 0 && g < 500) ? x[(b * 128 + c_occ[o]) * 500 + g] : 0.0f;
    }
    for (int i = tid; i < 16 * 189; i += 128) {
        int dc = i / 189, rem = i - dc * 189;
        int o = rem / 9, k = rem - o * 9;
        ws[(dc * 21 + o) * 12 + k] = wq[dg * 16 * 189 + i] * LOG2E;
    }
    __syncthreads();

    float acc0[16], acc1[16];
#pragma unroll
    for (int i = 0; i < 16; i++) { acc0[i] = 0.0f; acc1[i] = 0.0f; }

#pragma unroll 1
    for (int o = 0; o < 21; o++) {
        float xa[9], xb[9];
#pragma unroll
        for (int k = 0; k < 9; k++) {
            xa[k] = xo[o * 264 + tid + k];
            xb[k] = xo[o * 264 + tid + 128 + k];
        }
#pragma unroll
        for (int dc = 0; dc < 16; dc++) {
            const float* row = &ws[(dc * 21 + o) * 12];
            float4 wa = *reinterpret_cast<const float4*>(row);
            float4 wb = *reinterpret_cast<const float4*>(row + 4);
            float w8 = row[8];
            float a0 = acc0[dc], a1 = acc1[dc];
            a0 = fmaf(wa.x, xa[0], a0);  a1 = fmaf(wa.x, xb[0], a1);
            a0 = fmaf(wa.y, xa[1], a0);  a1 = fmaf(wa.y, xb[1], a1);
            a0 = fmaf(wa.z, xa[2], a0);  a1 = fmaf(wa.z, xb[2], a1);
            a0 = fmaf(wa.w, xa[3], a0);  a1 = fmaf(wa.w, xb[3], a1);
            a0 = fmaf(wb.x, xa[4], a0);  a1 = fmaf(wb.x, xb[4], a1);
            a0 = fmaf(wb.y, xa[5], a0);  a1 = fmaf(wb.y, xb[5], a1);
            a0 = fmaf(wb.z, xa[6], a0);  a1 = fmaf(wb.z, xb[6], a1);
            a0 = fmaf(wb.w, xa[7], a0);  a1 = fmaf(wb.w, xb[7], a1);
            a0 = fmaf(w8,   xa[8], a0);  a1 = fmaf(w8,   xb[8], a1);
            acc0[dc] = a0; acc1[dc] = a1;
        }
    }

    const int t1 = tstart + tid;
    const int t2 = t1 + 128;
#pragma unroll
    for (int dc = 0; dc < 16; dc++) {
        int dch = dg * 16 + dc;
        if (t1 < 500) qout[(b * 128 + dch) * 500 + t1] = selu_s(acc0[dc]);
        if (t2 < 500) qout[(b * 128 + dch) * 500 + t2] = selu_s(acc1[dc]);
    }
}

// ---------------------------------------------------------------------------
// Fused layer kernel — EXACT R9 structure (proven 88.4 us/layer).
// grid (C=128, B=8), 256 threads.
//   tt = tid & 127 : t-chunk (4 consecutive t, 125 active)
//   hh = tid >> 7  : head half (heads hh*4 .. hh*4+3)
// wks row (12 floats): [k0..k7][k8, wp, v8, pad]  -> kc4 = LDS.128
// ---------------------------------------------------------------------------
__global__ __launch_bounds__(256)
void layer_kernel(const float* __restrict__ xin,
                  const float* __restrict__ q,
                  const float* __restrict__ wk,
                  const float* __restrict__ wv,
                  const float* __restrict__ wproj,
                  float* __restrict__ xout) {
    const int c = blockIdx.x, b = blockIdx.y, tid = threadIdx.x;
    const int tt = tid & 127;
    const int hh = tid >> 7;

    __shared__ __align__(16) float xs[508];       // x row padded by 4 each side
    __shared__ __align__(16) float wks[128 * 12]; // K w ×log2e + {k8,wp,v8}
    __shared__ __align__(16) float wvs[128 * 12]; // V w ×log2e (first 8)
    __shared__ __align__(16) float pacc[125 * 4]; // partial acc from half 1

    const float* xrow = xin + (b * 128 + c) * 500;
    for (int i = tid; i < 508; i += 256) {
        int g = i - 4;
        xs[i] = (g >= 0 && g < 500) ? xrow[g] : 0.0f;
    }
    const float* wkr = wk + c * 1152;
    const float* wvr = wv + c * 1152;
    for (int i = tid; i < 1152; i += 256) {
        int row = i / 9, kk = i - row * 9;
        wks[row * 12 + kk] = wkr[i] * LOG2E;
        float wvv = wvr[i] * LOG2E;
        if (kk < 8) wvs[row * 12 + kk] = wvv;
        else        wks[row * 12 + 10] = wvv;     // v8 slot
    }
    if (tid < 128) wks[tid * 12 + 9] = wproj[c * 128 + tid];
    __syncthreads();

    const bool active = (tt < 125);
    const int t0 = tt * 4;
    float acc[4] = {0.f, 0.f, 0.f, 0.f};
    float xw[12];

    if (active) {
#pragma unroll
        for (int i = 0; i < 12; i++) xw[i] = xs[t0 + i];

        const float* qbase = q + (size_t)(b * 128 + hh * 64) * 500 + t0;
        const int d0 = hh * 64;

#pragma unroll 1
        for (int h = 0; h < 4; h++) {
            float qk[4] = {0.f, 0.f, 0.f, 0.f};
            float pv[4] = {0.f, 0.f, 0.f, 0.f};
#pragma unroll 4
            for (int j = 0; j < 16; j++) {
                const int dd = d0 + h * 16 + j;
                const float* krow = &wks[dd * 12];
                const float* vrow = &wvs[dd * 12];

                float4 ka  = *reinterpret_cast<const float4*>(krow);
                float4 kb  = *reinterpret_cast<const float4*>(krow + 4);
                float4 kc4 = *reinterpret_cast<const float4*>(krow + 8); // {k8,wp,v8,-}
                float4 va  = *reinterpret_cast<const float4*>(vrow);
                float4 vb  = *reinterpret_cast<const float4*>(vrow + 4);

                float kk[4], vv[4];
#pragma unroll
                for (int u = 0; u < 4; u++) {
                    float k0 = ka.x * xw[u];
                    float v0 = va.x * xw[u];
                    k0 = fmaf(ka.y, xw[u + 1], k0);  v0 = fmaf(va.y, xw[u + 1], v0);
                    k0 = fmaf(ka.z, xw[u + 2], k0);  v0 = fmaf(va.z, xw[u + 2], v0);
                    k0 = fmaf(ka.w, xw[u + 3], k0);  v0 = fmaf(va.w, xw[u + 3], v0);
                    k0 = fmaf(kb.x, xw[u + 4], k0);  v0 = fmaf(vb.x, xw[u + 4], v0);
                    k0 = fmaf(kb.y, xw[u + 5], k0);  v0 = fmaf(vb.y, xw[u + 5], v0);
                    k0 = fmaf(kb.z, xw[u + 6], k0);  v0 = fmaf(vb.z, xw[u + 6], v0);
                    k0 = fmaf(kb.w, xw[u + 7], k0);  v0 = fmaf(vb.w, xw[u + 7], v0);
                    k0 = fmaf(kc4.x, xw[u + 8], k0); v0 = fmaf(kc4.z, xw[u + 8], v0);
                    kk[u] = k0; vv[u] = v0;
                }

                float4 qv = *reinterpret_cast<const float4*>(qbase + (h * 16 + j) * 500);
                qk[0] = fmaf(qv.x, selu_s(kk[0]), qk[0]);
                qk[1] = fmaf(qv.y, selu_s(kk[1]), qk[1]);
                qk[2] = fmaf(qv.z, selu_s(kk[2]), qk[2]);
                qk[3] = fmaf(qv.w, selu_s(kk[3]), qk[3]);

                float wp = kc4.y;
#pragma unroll
                for (int u = 0; u < 4; u++)
                    pv[u] = fmaf(wp, selu_s(vv[u]), pv[u]);
            }
#pragma unroll
            for (int u = 0; u < 4; u++) {
                float gate = selu_s(Q_SC * qk[u]);   // selu(0.25*qk)
                acc[u] = fmaf(gate, pv[u], acc[u]);
            }
        }

        if (hh == 1) {
            float4 pa = make_float4(acc[0], acc[1], acc[2], acc[3]);
            *reinterpret_cast<float4*>(&pacc[tt * 4]) = pa;
        }
    }
    __syncthreads();

    if (active && hh == 0) {
        float4 pa = *reinterpret_cast<const float4*>(&pacc[tt * 4]);
        acc[0] += pa.x; acc[1] += pa.y; acc[2] += pa.z; acc[3] += pa.w;
        float4 res;
        res.x = (xw[4] + selu_f(acc[0])) * RES_SC;
        res.y = (xw[5] + selu_f(acc[1])) * RES_SC;
        res.z = (xw[6] + selu_f(acc[2])) * RES_SC;
        res.w = (xw[7] + selu_f(acc[3])) * RES_SC;
        *reinterpret_cast<float4*>(xout + (size_t)(b * 128 + c) * 500 + t0) = res;
    }
}

// ---------------------------------------------------------------------------
// Head — EXACT R9 (grid (40, 8), 256 threads; proven config).
// ---------------------------------------------------------------------------
__global__ __launch_bounds__(256)
void head_kernel(const float* __restrict__ x, const float* __restrict__ wh,
                 const float* __restrict__ bh, float* __restrict__ out) {
    const int n = blockIdx.x, b = blockIdx.y, tid = threadIdx.x;
    const float4* xr = reinterpret_cast<const float4*>(x + (size_t)b * 64000);
    const float4* wr = reinterpret_cast<const float4*>(wh + (size_t)n * 64000);
    float sum = 0.0f;
    for (int i = tid; i < 16000; i += 256) {
        float4 a = xr[i], w = wr[i];
        sum += a.x * w.x + a.y * w.y + a.z * w.z + a.w * w.w;
    }
#pragma unroll
    for (int off = 16; off; off >>= 1)
        sum += __shfl_down_sync(0xffffffffu, sum, off);
    __shared__ float ps[8];
    if ((tid & 31) == 0) ps[tid >> 5] = sum;
    __syncthreads();
    if (tid < 8) {
        sum = ps[tid];
#pragma unroll
        for (int off = 4; off; off >>= 1)
            sum += __shfl_down_sync(0xffu, sum, off);
        if (tid == 0) out[b * 40 + n] = sum + bh[n];
    }
}

// ---------------------------------------------------------------------------
extern "C" void kernel_launch(void* const* d_in, const int* in_sizes, int n_in,
                              void* d_out, int out_size) {
    const float* x     = (const float*)d_in[0];
    const float* wq    = (const float*)d_in[2];  // (2,128,21,9)
    const float* wk    = (const float*)d_in[3];  // (2,16384,1,9)
    const float* wv    = (const float*)d_in[4];  // (2,16384,1,9)
    const float* wproj = (const float*)d_in[5];  // (2,128,128)
    const float* whead = (const float*)d_in[6];  // (40,64000)
    const float* bhead = (const float*)d_in[7];  // (40,)
    float* out = (float*)d_out;

    float *gx = nullptr, *gq = nullptr;
    cudaGetSymbolAddress((void**)&gx, g_x);
    cudaGetSymbolAddress((void**)&gq, g_q);

    dim3 qg(8, 2, 8);
    dim3 lg(128, 8);
    dim3 hg(40, 8);

    q_kernel<<<qg, 128>>>(x, wq, gq);
    layer_kernel<<<lg, 256>>>(x, gq, wk, wv, wproj, gx);
    q_kernel<<<qg, 128>>>(gx, wq + 24192, gq);
    layer_kernel<<<lg, 256>>>(gx, gq, wk + 147456, wv + 147456,
                              wproj + 16384, gx);
    head_kernel<<<hg, 256>>>(gx, whead, bhead, out);
}

// round 17
// speedup vs baseline: 2.6519x; 1.0197x over previous
#include <cuda_runtime.h>

#define SELU_SC 1.0507009873554805f
#define SELU_AL 1.6732632423543772f
#define SELU_SA (SELU_SC * SELU_AL)
#define RES_SC  0.70710678118654752440f
#define LOG2E   1.4426950408889634f
#define LN2     0.6931471805599453f
#define SC_LN2  (SELU_SC * LN2)
#define Q_SC    (0.25f * LOG2E)

// standard branch-free selu (for unscaled inputs)
__device__ __forceinline__ float selu_f(float v) {
    float p = fmaxf(v, 0.0f);
    float m = fminf(v, 0.0f);
    float e = __expf(m);
    return fmaf(SELU_SA, e, fmaf(SELU_SC, p, -SELU_SA));
}

// selu on pre-scaled input s = v*log2e  (weights pre-multiplied by log2e)
__device__ __forceinline__ float selu_s(float s) {
    float p = fmaxf(s, 0.0f);
    float m = fminf(s, 0.0f);
    float e;
    asm("ex2.approx.ftz.f32 %0, %1;" : "=f"(e) : "f"(m));
    return fmaf(SELU_SA, e, fmaf(SC_LN2, p, -SELU_SA));
}

__constant__ int c_occ[21] = {65,66,67,68,69,70,71,72,73,74,75,76,77,
                              81,82,83,84,88,89,90,94};

// scratch (no cudaMalloc allowed)
__device__ float g_x[8 * 128 * 500];
__device__ float g_q[8 * 128 * 500];

// ---------------------------------------------------------------------------
// Q kernel v4 (R16, proven): grid (8 dg, 2 t-tiles of 256, 8 b), 128 threads,
// 2 t x 16 dch per thread, padded 12-float weight rows (x LOG2E).
// ---------------------------------------------------------------------------
__global__ __launch_bounds__(128)
void q_kernel(const float* __restrict__ x, const float* __restrict__ wq,
              float* __restrict__ qout) {
    const int dg = blockIdx.x;            // 16-dch group
    const int tstart = blockIdx.y * 256;  // t tile
    const int b = blockIdx.z;
    const int tid = threadIdx.x;

    __shared__ float xo[21 * 264];
    __shared__ __align__(16) float ws[16 * 21 * 12];  // padded weight rows

    for (int i = tid; i < 21 * 264; i += 128) {
        int o = i / 264, tt = i % 264;
        int g = tstart + tt - 4;
        xo[i] = (g >= 0 && g < 500) ? x[(b * 128 + c_occ[o]) * 500 + g] : 0.0f;
    }
    for (int i = tid; i < 16 * 189; i += 128) {
        int dc = i / 189, rem = i - dc * 189;
        int o = rem / 9, k = rem - o * 9;
        ws[(dc * 21 + o) * 12 + k] = wq[dg * 16 * 189 + i] * LOG2E;
    }
    __syncthreads();

    float acc0[16], acc1[16];
#pragma unroll
    for (int i = 0; i < 16; i++) { acc0[i] = 0.0f; acc1[i] = 0.0f; }

#pragma unroll 1
    for (int o = 0; o < 21; o++) {
        float xa[9], xb[9];
#pragma unroll
        for (int k = 0; k < 9; k++) {
            xa[k] = xo[o * 264 + tid + k];
            xb[k] = xo[o * 264 + tid + 128 + k];
        }
#pragma unroll
        for (int dc = 0; dc < 16; dc++) {
            const float* row = &ws[(dc * 21 + o) * 12];
            float4 wa = *reinterpret_cast<const float4*>(row);
            float4 wb = *reinterpret_cast<const float4*>(row + 4);
            float w8 = row[8];
            float a0 = acc0[dc], a1 = acc1[dc];
            a0 = fmaf(wa.x, xa[0], a0);  a1 = fmaf(wa.x, xb[0], a1);
            a0 = fmaf(wa.y, xa[1], a0);  a1 = fmaf(wa.y, xb[1], a1);
            a0 = fmaf(wa.z, xa[2], a0);  a1 = fmaf(wa.z, xb[2], a1);
            a0 = fmaf(wa.w, xa[3], a0);  a1 = fmaf(wa.w, xb[3], a1);
            a0 = fmaf(wb.x, xa[4], a0);  a1 = fmaf(wb.x, xb[4], a1);
            a0 = fmaf(wb.y, xa[5], a0);  a1 = fmaf(wb.y, xb[5], a1);
            a0 = fmaf(wb.z, xa[6], a0);  a1 = fmaf(wb.z, xb[6], a1);
            a0 = fmaf(wb.w, xa[7], a0);  a1 = fmaf(wb.w, xb[7], a1);
            a0 = fmaf(w8,   xa[8], a0);  a1 = fmaf(w8,   xb[8], a1);
            acc0[dc] = a0; acc1[dc] = a1;
        }
    }

    const int t1 = tstart + tid;
    const int t2 = t1 + 128;
#pragma unroll
    for (int dc = 0; dc < 16; dc++) {
        int dch = dg * 16 + dc;
        if (t1 < 500) qout[(b * 128 + dch) * 500 + t1] = selu_s(acc0[dc]);
        if (t2 < 500) qout[(b * 128 + dch) * 500 + t2] = selu_s(acc1[dc]);
    }
}

// ---------------------------------------------------------------------------
// Fused layer kernel — EXACT R9/R16 structure (proven).
// grid (C=128, B=8), 256 threads.
// ---------------------------------------------------------------------------
__global__ __launch_bounds__(256)
void layer_kernel(const float* __restrict__ xin,
                  const float* __restrict__ q,
                  const float* __restrict__ wk,
                  const float* __restrict__ wv,
                  const float* __restrict__ wproj,
                  float* __restrict__ xout) {
    const int c = blockIdx.x, b = blockIdx.y, tid = threadIdx.x;
    const int tt = tid & 127;
    const int hh = tid >> 7;

    __shared__ __align__(16) float xs[508];       // x row padded by 4 each side
    __shared__ __align__(16) float wks[128 * 12]; // K w ×log2e + {k8,wp,v8}
    __shared__ __align__(16) float wvs[128 * 12]; // V w ×log2e (first 8)
    __shared__ __align__(16) float pacc[125 * 4]; // partial acc from half 1

    const float* xrow = xin + (b * 128 + c) * 500;
    for (int i = tid; i < 508; i += 256) {
        int g = i - 4;
        xs[i] = (g >= 0 && g < 500) ? xrow[g] : 0.0f;
    }
    const float* wkr = wk + c * 1152;
    const float* wvr = wv + c * 1152;
    for (int i = tid; i < 1152; i += 256) {
        int row = i / 9, kk = i - row * 9;
        wks[row * 12 + kk] = wkr[i] * LOG2E;
        float wvv = wvr[i] * LOG2E;
        if (kk < 8) wvs[row * 12 + kk] = wvv;
        else        wks[row * 12 + 10] = wvv;     // v8 slot
    }
    if (tid < 128) wks[tid * 12 + 9] = wproj[c * 128 + tid];
    __syncthreads();

    const bool active = (tt < 125);
    const int t0 = tt * 4;
    float acc[4] = {0.f, 0.f, 0.f, 0.f};
    float xw[12];

    if (active) {
#pragma unroll
        for (int i = 0; i < 12; i++) xw[i] = xs[t0 + i];

        const float* qbase = q + (size_t)(b * 128 + hh * 64) * 500 + t0;
        const int d0 = hh * 64;

#pragma unroll 1
        for (int h = 0; h < 4; h++) {
            float qk[4] = {0.f, 0.f, 0.f, 0.f};
            float pv[4] = {0.f, 0.f, 0.f, 0.f};
#pragma unroll 4
            for (int j = 0; j < 16; j++) {
                const int dd = d0 + h * 16 + j;
                const float* krow = &wks[dd * 12];
                const float* vrow = &wvs[dd * 12];

                float4 ka  = *reinterpret_cast<const float4*>(krow);
                float4 kb  = *reinterpret_cast<const float4*>(krow + 4);
                float4 kc4 = *reinterpret_cast<const float4*>(krow + 8); // {k8,wp,v8,-}
                float4 va  = *reinterpret_cast<const float4*>(vrow);
                float4 vb  = *reinterpret_cast<const float4*>(vrow + 4);

                float kk[4], vv[4];
#pragma unroll
                for (int u = 0; u < 4; u++) {
                    float k0 = ka.x * xw[u];
                    float v0 = va.x * xw[u];
                    k0 = fmaf(ka.y, xw[u + 1], k0);  v0 = fmaf(va.y, xw[u + 1], v0);
                    k0 = fmaf(ka.z, xw[u + 2], k0);  v0 = fmaf(va.z, xw[u + 2], v0);
                    k0 = fmaf(ka.w, xw[u + 3], k0);  v0 = fmaf(va.w, xw[u + 3], v0);
                    k0 = fmaf(kb.x, xw[u + 4], k0);  v0 = fmaf(vb.x, xw[u + 4], v0);
                    k0 = fmaf(kb.y, xw[u + 5], k0);  v0 = fmaf(vb.y, xw[u + 5], v0);
                    k0 = fmaf(kb.z, xw[u + 6], k0);  v0 = fmaf(vb.z, xw[u + 6], v0);
                    k0 = fmaf(kb.w, xw[u + 7], k0);  v0 = fmaf(vb.w, xw[u + 7], v0);
                    k0 = fmaf(kc4.x, xw[u + 8], k0); v0 = fmaf(kc4.z, xw[u + 8], v0);
                    kk[u] = k0; vv[u] = v0;
                }

                float4 qv = *reinterpret_cast<const float4*>(qbase + (h * 16 + j) * 500);
                qk[0] = fmaf(qv.x, selu_s(kk[0]), qk[0]);
                qk[1] = fmaf(qv.y, selu_s(kk[1]), qk[1]);
                qk[2] = fmaf(qv.z, selu_s(kk[2]), qk[2]);
                qk[3] = fmaf(qv.w, selu_s(kk[3]), qk[3]);

                float wp = kc4.y;
#pragma unroll
                for (int u = 0; u < 4; u++)
                    pv[u] = fmaf(wp, selu_s(vv[u]), pv[u]);
            }
#pragma unroll
            for (int u = 0; u < 4; u++) {
                float gate = selu_s(Q_SC * qk[u]);   // selu(0.25*qk)
                acc[u] = fmaf(gate, pv[u], acc[u]);
            }
        }

        if (hh == 1) {
            float4 pa = make_float4(acc[0], acc[1], acc[2], acc[3]);
            *reinterpret_cast<float4*>(&pacc[tt * 4]) = pa;
        }
    }
    __syncthreads();

    if (active && hh == 0) {
        float4 pa = *reinterpret_cast<const float4*>(&pacc[tt * 4]);
        acc[0] += pa.x; acc[1] += pa.y; acc[2] += pa.z; acc[3] += pa.w;
        float4 res;
        res.x = (xw[4] + selu_f(acc[0])) * RES_SC;
        res.y = (xw[5] + selu_f(acc[1])) * RES_SC;
        res.z = (xw[6] + selu_f(acc[2])) * RES_SC;
        res.w = (xw[7] + selu_f(acc[3])) * RES_SC;
        *reinterpret_cast<float4*>(xout + (size_t)(b * 128 + c) * 500 + t0) = res;
    }
}

// ---------------------------------------------------------------------------
// Head v4: 2 heads per block, 512 threads; grid (20, 8).
// Total warps preserved vs R9 (2560) while halving x-slab re-reads.
// ---------------------------------------------------------------------------
__global__ __launch_bounds__(512)
void head_kernel(const float* __restrict__ x, const float* __restrict__ wh,
                 const float* __restrict__ bh, float* __restrict__ out) {
    const int n0 = blockIdx.x * 2, b = blockIdx.y, tid = threadIdx.x;
    const float4* xr = reinterpret_cast<const float4*>(x + (size_t)b * 64000);
    const float4* w0 = reinterpret_cast<const float4*>(wh + (size_t)(n0 + 0) * 64000);
    const float4* w1 = reinterpret_cast<const float4*>(wh + (size_t)(n0 + 1) * 64000);

    float s0 = 0.f, s1 = 0.f;
    for (int i = tid; i < 16000; i += 512) {
        float4 a = xr[i];
        float4 w = w0[i];
        s0 += a.x * w.x + a.y * w.y + a.z * w.z + a.w * w.w;
        w = w1[i];
        s1 += a.x * w.x + a.y * w.y + a.z * w.z + a.w * w.w;
    }
#pragma unroll
    for (int off = 16; off; off >>= 1) {
        s0 += __shfl_down_sync(0xffffffffu, s0, off);
        s1 += __shfl_down_sync(0xffffffffu, s1, off);
    }
    __shared__ float ps[16][2];
    if ((tid & 31) == 0) {
        int w = tid >> 5;
        ps[w][0] = s0; ps[w][1] = s1;
    }
    __syncthreads();
    if (tid < 2) {
        float sum = 0.f;
#pragma unroll
        for (int w = 0; w < 16; w++) sum += ps[w][tid];
        out[b * 40 + n0 + tid] = sum + bh[n0 + tid];
    }
}

// ---------------------------------------------------------------------------
extern "C" void kernel_launch(void* const* d_in, const int* in_sizes, int n_in,
                              void* d_out, int out_size) {
    const float* x     = (const float*)d_in[0];
    const float* wq    = (const float*)d_in[2];  // (2,128,21,9)
    const float* wk    = (const float*)d_in[3];  // (2,16384,1,9)
    const float* wv    = (const float*)d_in[4];  // (2,16384,1,9)
    const float* wproj = (const float*)d_in[5];  // (2,128,128)
    const float* whead = (const float*)d_in[6];  // (40,64000)
    const float* bhead = (const float*)d_in[7];  // (40,)
    float* out = (float*)d_out;

    float *gx = nullptr, *gq = nullptr;
    cudaGetSymbolAddress((void**)&gx, g_x);
    cudaGetSymbolAddress((void**)&gq, g_q);

    dim3 qg(8, 2, 8);
    dim3 lg(128, 8);
    dim3 hg(20, 8);

    q_kernel<<<qg, 128>>>(x, wq, gq);
    layer_kernel<<<lg, 256>>>(x, gq, wk, wv, wproj, gx);
    q_kernel<<<qg, 128>>>(gx, wq + 24192, gq);
    layer_kernel<<<lg, 256>>>(gx, gq, wk + 147456, wv + 147456,
                              wproj + 16384, gx);
    head_kernel<<<hg, 512>>>(gx, whead, bhead, out);
}